// round 2
// baseline (speedup 1.0000x reference)
#include <cuda_runtime.h>
#include <cuda_bf16.h>
#include <cstdint>

// Problem constants
#define BS     2
#define NM     10
#define NA     8400
#define NC     80
#define NPT    360
#define NBINS  36
#define BSNMNA (BS*NM*NA)
#define BSNA   (BS*NA)

// Output layout (flat float32, reference tuple order)
#define TL_OFF      0            // target_labels   (2,8400)        16800
#define TB_OFF      16800        // target_bboxes   (2,8400,4)      67200
#define TS_OFF      84000        // target_scores   (2,8400,80)     1344000
#define MPB_OFF     1428000      // mask_pos_b      (2,10,8400)     168000
#define TGI_OFF     1596000      // target_gt_idx   (2,8400)        16800
#define GTDIST_OFF  1612800      // gt_dist         (2,10,8400,36)  6048000
#define CENT_OFF    7660800      // centerness_gt   (2,10,8400)     168000
#define FG_OFF      7828800      // fg_mask         (2,8400)        16800
#define OUT_TOTAL   7845600

// Scratch (device globals; zeroed per launch where required)
__device__ float g_align[BSNMNA];
__device__ float g_overlaps[BSNMNA];
__device__ float g_maskpos[BSNMNA];
__device__ float g_cent[BSNMNA];
__device__ unsigned char g_maskin[BSNMNA];
__device__ unsigned long long g_key[BSNMNA];
__device__ float g_posAlign[BS*NM];
__device__ float g_posOv[BS*NM];

__device__ __forceinline__ unsigned long long ullmin2(unsigned long long a, unsigned long long b){ return a<b?a:b; }
__device__ __forceinline__ unsigned long long ullmax2(unsigned long long a, unsigned long long b){ return a>b?a:b; }

// ---------------------------------------------------------------------------
// K0: zero output + scratch
// ---------------------------------------------------------------------------
__global__ void k_zero(float* __restrict__ out) {
    int i = blockIdx.x * blockDim.x + threadIdx.x;
    if (i < OUT_TOTAL) out[i] = 0.f;
    if (i < BSNMNA) {
        g_align[i] = 0.f;
        g_overlaps[i] = 0.f;
        g_maskpos[i] = 0.f;
        g_maskin[i] = 0;
    }
}

// ---------------------------------------------------------------------------
// K1: per (gt, anchor-tile) — dist_max per bin, iou, align metric, centerness
// ---------------------------------------------------------------------------
__global__ __launch_bounds__(128) void k_pairs(
    const float* __restrict__ pd_scores,
    const float* __restrict__ pd_bboxes,
    const float* __restrict__ anc,
    const int*   __restrict__ gt_labels,
    const float* __restrict__ gt_bboxes,
    const float* __restrict__ mask_gt,
    const float* __restrict__ gt_coor,
    float* __restrict__ out)
{
    int bm = blockIdx.y;
    if (mask_gt[bm] == 0.f) return;
    int b = bm / NM;

    __shared__ float sx[NPT], sy[NPT], sdist[NPT], sang[NPT];
    __shared__ float sdm[NBINS];

    const float* gp = gt_coor + (size_t)bm * (2*NPT);
    for (int p = threadIdx.x; p < NPT; p += blockDim.x) {
        sx[p] = gp[2*p];
        sy[p] = gp[2*p+1];
    }
    float lx = gt_bboxes[bm*4+0], ly = gt_bboxes[bm*4+1];
    float rx = gt_bboxes[bm*4+2], ry = gt_bboxes[bm*4+3];
    int label = gt_labels[bm];
    __syncthreads();

    int lane = threadIdx.x & 31;
    int warp = threadIdx.x >> 5;

    for (int a = blockIdx.x; a < NA; a += gridDim.x) {
        float ax = anc[2*a], ay = anc[2*a+1];
        float mind = fminf(fminf(ax-lx, ay-ly), fminf(rx-ax, ry-ay));
        if (!(mind > 1e-9f)) continue;   // uniform per block

        int pairIdx = bm * NA + a;
        if (threadIdx.x == 0) g_maskin[pairIdx] = 1;

        // point phase: distance + angle (deg, [0,360))
        for (int p = threadIdx.x; p < NPT; p += blockDim.x) {
            float dx = sx[p] - ax, dy = sy[p] - ay;
            sdist[p] = sqrtf(dx*dx + dy*dy);
            float ang = atan2f(dy, dx) * 57.29577951308232f;
            if (ang < 0.f) ang += 360.f;
            sang[p] = ang;
        }
        __syncthreads();

        // bin phase: each warp handles bins warp, warp+4, ...
        for (int bin = warp; bin < NBINS; bin += 4) {
            float th = (float)(bin * 10);
            unsigned long long key[12];
            #pragma unroll
            for (int j = 0; j < 12; j++) {
                int p = lane + 32*j;
                if (p < NPT) {
                    float df = fabsf(sang[p] - th);
                    if (df > 180.f) df = 360.f - df;
                    key[j] = ((unsigned long long)__float_as_uint(df) << 32) | (unsigned)p;
                } else {
                    key[j] = ~0ull;
                }
            }
            float mindiff = 0.f;
            float dmax = 0.f;
            #pragma unroll
            for (int k = 0; k < 4; k++) {
                unsigned long long lk = ~0ull;
                #pragma unroll
                for (int j = 0; j < 12; j++) lk = ullmin2(lk, key[j]);
                #pragma unroll
                for (int off = 16; off; off >>= 1)
                    lk = ullmin2(lk, __shfl_xor_sync(0xffffffffu, lk, off));
                int widx = (int)(lk & 0xffffffffu);
                if (k == 0) mindiff = __uint_as_float((unsigned)(lk >> 32));
                dmax = fmaxf(dmax, sdist[widx]);
                #pragma unroll
                for (int j = 0; j < 12; j++) if (key[j] == lk) key[j] = ~0ull;
            }
            float dm = (mindiff > 3.0f) ? 1e-6f : dmax;
            dm = fmaxf(dm, 1e-6f);
            if (lane == 0) sdm[bin] = dm;
        }
        __syncthreads();

        // write dist_max straight into gt_dist region (masked later)
        if (threadIdx.x < NBINS)
            out[GTDIST_OFF + (size_t)pairIdx * NBINS + threadIdx.x] = sdm[threadIdx.x];

        // warp 0: iou + centerness + align metric
        if (warp == 0) {
            float smin = 0.f, smax = 0.f, mn = 1e30f, mx = 0.f;
            const float* pb = pd_bboxes + ((size_t)b*NA + a) * NBINS;
            for (int e = lane; e < NBINS; e += 32) {
                float t = sdm[e], p = pb[e];
                smin += fmaxf(fminf(t, p), 1e-6f);
                smax += fmaxf(t, p);
                mn = fminf(mn, t);
                mx = fmaxf(mx, t);
            }
            #pragma unroll
            for (int off = 16; off; off >>= 1) {
                smin += __shfl_xor_sync(0xffffffffu, smin, off);
                smax += __shfl_xor_sync(0xffffffffu, smax, off);
                mn = fminf(mn, __shfl_xor_sync(0xffffffffu, mn, off));
                mx = fmaxf(mx, __shfl_xor_sync(0xffffffffu, mx, off));
            }
            if (lane == 0) {
                float iou = smin / smax;
                float score = pd_scores[((size_t)b*NA + a) * NC + label];
                g_overlaps[pairIdx] = iou;
                g_align[pairIdx]    = score * iou * iou * iou;
                g_cent[pairIdx]     = sqrtf(mn / mx);
            }
        }
        __syncthreads();
    }
}

// ---------------------------------------------------------------------------
// K2: top-13 per (b,m) with exact JAX tie semantics (val desc, idx asc)
// ---------------------------------------------------------------------------
__global__ __launch_bounds__(256) void k_topk(const float* __restrict__ mask_gt) {
    int bm = blockIdx.x;
    if (mask_gt[bm] == 0.f) return;
    int tid = threadIdx.x;
    __shared__ unsigned long long sred[8];

    unsigned long long* row = g_key + (size_t)bm * NA;
    for (int a = tid; a < NA; a += 256) {
        float v = g_align[bm*NA + a];
        row[a] = ((unsigned long long)__float_as_uint(v) << 32) | (unsigned)(NA - a);
    }
    __syncthreads();

    for (int k = 0; k < 13; k++) {
        unsigned long long best = 0;
        for (int a = tid; a < NA; a += 256) best = ullmax2(best, row[a]);
        #pragma unroll
        for (int off = 16; off; off >>= 1)
            best = ullmax2(best, __shfl_xor_sync(0xffffffffu, best, off));
        if ((tid & 31) == 0) sred[tid >> 5] = best;
        __syncthreads();
        if (tid == 0) {
            unsigned long long b2 = 0;
            #pragma unroll
            for (int w = 0; w < 8; w++) b2 = ullmax2(b2, sred[w]);
            int widx = NA - (int)(b2 & 0xffffffffu);
            row[widx] = 0;  // exclude for next pass
            // mask_topk=1 for chosen; mask_pos = topk * in_gts * mgt
            g_maskpos[bm*NA + widx] = g_maskin[bm*NA + widx] ? 1.f : 0.f;
        }
        __syncthreads();
    }
}

// ---------------------------------------------------------------------------
// K3: per-anchor column resolution + most outputs
// ---------------------------------------------------------------------------
__global__ __launch_bounds__(256) void k_assign(
    const int*   __restrict__ gt_labels,
    const float* __restrict__ gt_bboxes,
    float* __restrict__ out)
{
    int t = blockIdx.x * blockDim.x + threadIdx.x;
    if (t >= BSNA) return;
    int b = t / NA, a = t % NA;

    float mp[NM];
    float fg = 0.f;
    #pragma unroll
    for (int m = 0; m < NM; m++) { mp[m] = g_maskpos[(b*NM+m)*NA + a]; fg += mp[m]; }

    if (fg > 1.f) {
        float best = -1.f; int bi = 0;
        #pragma unroll
        for (int m = 0; m < NM; m++) {
            float o = g_overlaps[(b*NM+m)*NA + a];
            if (o > best) { best = o; bi = m; }     // first max kept
        }
        #pragma unroll
        for (int m = 0; m < NM; m++) mp[m] = (m == bi) ? 1.f : 0.f;
    }

    float fg2 = 0.f; int tgt = 0; bool found = false;
    #pragma unroll
    for (int m = 0; m < NM; m++) {
        fg2 += mp[m];
        if (!found && mp[m] > 0.f) { tgt = m; found = true; }
    }

    #pragma unroll
    for (int m = 0; m < NM; m++) {
        int idx = (b*NM+m)*NA + a;
        g_maskpos[idx] = mp[m];
        bool pos = mp[m] > 0.f;
        out[MPB_OFF + idx]  = pos ? 1.f : 0.f;
        out[CENT_OFF + idx] = pos ? g_cent[idx] : 0.f;
        if (g_maskin[idx] && !pos) {
            float* gd = out + GTDIST_OFF + (size_t)idx * NBINS;
            #pragma unroll
            for (int e = 0; e < NBINS; e++) gd[e] = 0.f;
        }
    }

    out[FG_OFF + t]  = (fg2 > 0.f) ? 1.f : 0.f;
    out[TGI_OFF + t] = (float)tgt;
    int lbl = gt_labels[b*NM + tgt]; if (lbl < 0) lbl = 0;
    out[TL_OFF + t] = (float)lbl;
    #pragma unroll
    for (int e = 0; e < 4; e++)
        out[TB_OFF + t*4 + e] = gt_bboxes[(b*NM + tgt)*4 + e];
}

// ---------------------------------------------------------------------------
// K4: per-(b,m) pos_align / pos_overlaps maxima
// ---------------------------------------------------------------------------
__global__ __launch_bounds__(256) void k_posmax() {
    int bm = blockIdx.x;
    int tid = threadIdx.x;
    __shared__ float s1[8], s2[8];
    float pa = 0.f, po = 0.f;
    for (int a = tid; a < NA; a += 256) {
        float mpv = g_maskpos[bm*NA + a];
        pa = fmaxf(pa, g_align[bm*NA + a] * mpv);
        po = fmaxf(po, g_overlaps[bm*NA + a] * mpv);
    }
    #pragma unroll
    for (int off = 16; off; off >>= 1) {
        pa = fmaxf(pa, __shfl_xor_sync(0xffffffffu, pa, off));
        po = fmaxf(po, __shfl_xor_sync(0xffffffffu, po, off));
    }
    if ((tid & 31) == 0) { s1[tid>>5] = pa; s2[tid>>5] = po; }
    __syncthreads();
    if (tid == 0) {
        float a1 = 0.f, a2 = 0.f;
        #pragma unroll
        for (int w = 0; w < 8; w++) { a1 = fmaxf(a1, s1[w]); a2 = fmaxf(a2, s2[w]); }
        g_posAlign[bm] = a1;
        g_posOv[bm]    = a2;
    }
}

// ---------------------------------------------------------------------------
// K5: norm_align + target_scores one-hot write
// ---------------------------------------------------------------------------
__global__ __launch_bounds__(256) void k_scores(float* __restrict__ out) {
    int t = blockIdx.x * blockDim.x + threadIdx.x;
    if (t >= BSNA) return;
    int b = t / NA, a = t % NA;
    float norm = 0.f;
    #pragma unroll
    for (int m = 0; m < NM; m++) {
        int idx = (b*NM+m)*NA + a;
        float am = g_align[idx] * g_maskpos[idx];
        float v = am * g_posOv[b*NM+m] / (g_posAlign[b*NM+m] + 1e-9f);
        norm = fmaxf(norm, v);
    }
    if (out[FG_OFF + t] > 0.f) {
        int lbl = (int)out[TL_OFF + t];
        out[TS_OFF + (size_t)t * NC + lbl] = norm;
    }
}

// ---------------------------------------------------------------------------
extern "C" void kernel_launch(void* const* d_in, const int* in_sizes, int n_in,
                              void* d_out, int out_size) {
    const float* pd_scores = (const float*)d_in[0];
    const float* pd_bboxes = (const float*)d_in[1];
    const float* anc       = (const float*)d_in[2];
    const int*   gt_labels = (const int*)  d_in[3];
    const float* gt_bboxes = (const float*)d_in[4];
    const float* mask_gt   = (const float*)d_in[5];
    const float* gt_coor   = (const float*)d_in[6];
    float* out = (float*)d_out;

    k_zero<<<(OUT_TOTAL + 255)/256, 256>>>(out);
    dim3 g1(64, BS*NM);
    k_pairs<<<g1, 128>>>(pd_scores, pd_bboxes, anc, gt_labels, gt_bboxes, mask_gt, gt_coor, out);
    k_topk<<<BS*NM, 256>>>(mask_gt);
    k_assign<<<(BSNA + 255)/256, 256>>>(gt_labels, gt_bboxes, out);
    k_posmax<<<BS*NM, 256>>>();
    k_scores<<<(BSNA + 255)/256, 256>>>(out);
}

// round 3
// speedup vs baseline: 2.4210x; 2.4210x over previous
#include <cuda_runtime.h>
#include <cuda_bf16.h>
#include <cstdint>

// Problem constants
#define BS     2
#define NM     10
#define NA     8400
#define NC     80
#define NPT    360
#define NBINS  36
#define NBM    (BS*NM)
#define BSNMNA (BS*NM*NA)
#define BSNA   (BS*NA)
#define MAXL   1024

// Output layout (flat float32, reference tuple order)
#define TL_OFF      0            // target_labels   (2,8400)        16800
#define TB_OFF      16800        // target_bboxes   (2,8400,4)      67200
#define TS_OFF      84000        // target_scores   (2,8400,80)     1344000
#define MPB_OFF     1428000      // mask_pos_b      (2,10,8400)     168000
#define TGI_OFF     1596000      // target_gt_idx   (2,8400)        16800
#define GTDIST_OFF  1612800      // gt_dist         (2,10,8400,36)  6048000
#define CENT_OFF    7660800      // centerness_gt   (2,10,8400)     168000
#define FG_OFF      7828800      // fg_mask         (2,8400)        16800
#define OUT_TOTAL   7845600
#define OUT_VEC4    (OUT_TOTAL/4)   // 1961400, exact

// Scratch (device globals). Written only at live entries; read only at
// positive entries (pos ⊆ live), so no per-launch zeroing needed except
// the small bitmask/counter arrays.
__device__ float g_align[BSNMNA];
__device__ float g_overlaps[BSNMNA];
__device__ float g_cent[BSNMNA];
__device__ float g_dist[(size_t)BSNMNA * NBINS];
__device__ int   g_liveA[NBM * MAXL];
__device__ int   g_cnt[NBM];
__device__ unsigned g_inbits[BSNA];
__device__ unsigned g_topkbits[BSNA];
__device__ unsigned g_finbits[BSNA];
__device__ unsigned g_posA[NBM];   // float bits, nonneg -> uint order == float order
__device__ unsigned g_posO[NBM];

__device__ __forceinline__ unsigned long long ullmin2(unsigned long long a, unsigned long long b){ return a<b?a:b; }
__device__ __forceinline__ unsigned long long ullmax2(unsigned long long a, unsigned long long b){ return a>b?a:b; }

// ---------------------------------------------------------------------------
// K0: zero output (vectorized) + small scratch
// ---------------------------------------------------------------------------
__global__ void k_zero(float4* __restrict__ out4) {
    int i = blockIdx.x * blockDim.x + threadIdx.x;
    if (i < OUT_VEC4) out4[i] = make_float4(0.f, 0.f, 0.f, 0.f);
    if (i < BSNA) g_topkbits[i] = 0u;
    if (i < NBM) { g_cnt[i] = 0; g_posA[i] = 0u; g_posO[i] = 0u; }
}

// ---------------------------------------------------------------------------
// K1: per-anchor in-box bitmask + per-GT compacted live lists
// ---------------------------------------------------------------------------
__global__ __launch_bounds__(256) void k_compact(
    const float* __restrict__ anc,
    const float* __restrict__ gt_bboxes,
    const float* __restrict__ mask_gt)
{
    __shared__ float sbox[NBM][4];
    __shared__ float smgt[NBM];
    if (threadIdx.x < NBM) {
        sbox[threadIdx.x][0] = gt_bboxes[threadIdx.x*4+0];
        sbox[threadIdx.x][1] = gt_bboxes[threadIdx.x*4+1];
        sbox[threadIdx.x][2] = gt_bboxes[threadIdx.x*4+2];
        sbox[threadIdx.x][3] = gt_bboxes[threadIdx.x*4+3];
        smgt[threadIdx.x] = mask_gt[threadIdx.x];
    }
    __syncthreads();
    int t = blockIdx.x * blockDim.x + threadIdx.x;
    if (t >= BSNA) return;
    int b = t / NA, a = t % NA;
    float ax = anc[2*a], ay = anc[2*a+1];
    unsigned inb = 0;
    #pragma unroll
    for (int m = 0; m < NM; m++) {
        int bm = b*NM + m;
        if (smgt[bm] == 0.f) continue;
        float mind = fminf(fminf(ax - sbox[bm][0], ay - sbox[bm][1]),
                           fminf(sbox[bm][2] - ax, sbox[bm][3] - ay));
        if (mind > 1e-9f) {
            inb |= (1u << m);
            int s = atomicAdd(&g_cnt[bm], 1);
            if (s < MAXL) g_liveA[bm*MAXL + s] = a;
        }
    }
    g_inbits[t] = inb;
}

// ---------------------------------------------------------------------------
// K2: heavy per-pair work on live pairs only
// ---------------------------------------------------------------------------
__global__ __launch_bounds__(128) void k_pairs(
    const float* __restrict__ pd_scores,
    const float* __restrict__ pd_bboxes,
    const float* __restrict__ anc,
    const int*   __restrict__ gt_labels,
    const float* __restrict__ gt_coor)
{
    int bm = blockIdx.y;
    int cnt = g_cnt[bm];
    if (cnt == 0) return;
    if (cnt > MAXL) cnt = MAXL;
    int b = bm / NM;

    __shared__ float sx[NPT], sy[NPT], sdist[NPT], sang[NPT];
    __shared__ float sdm[NBINS];

    const float* gp = gt_coor + (size_t)bm * (2*NPT);
    for (int p = threadIdx.x; p < NPT; p += blockDim.x) {
        sx[p] = gp[2*p];
        sy[p] = gp[2*p+1];
    }
    int label = gt_labels[bm];
    __syncthreads();

    int lane = threadIdx.x & 31;
    int warp = threadIdx.x >> 5;

    for (int j = blockIdx.x; j < cnt; j += gridDim.x) {
        int a = g_liveA[bm*MAXL + j];
        float ax = anc[2*a], ay = anc[2*a+1];
        int pairIdx = bm * NA + a;

        // point phase: distance + angle (deg, [0,360))
        for (int p = threadIdx.x; p < NPT; p += blockDim.x) {
            float dx = sx[p] - ax, dy = sy[p] - ay;
            sdist[p] = sqrtf(dx*dx + dy*dy);
            float ang = atan2f(dy, dx) * 57.29577951308232f;
            if (ang < 0.f) ang += 360.f;
            sang[p] = ang;
        }
        __syncthreads();

        // bin phase: warp w handles bins w, w+4, ...
        for (int bin = warp; bin < NBINS; bin += 4) {
            float th = (float)(bin * 10);
            unsigned long long key[12];
            #pragma unroll
            for (int jj = 0; jj < 12; jj++) {
                int p = lane + 32*jj;
                if (p < NPT) {
                    float df = fabsf(sang[p] - th);
                    if (df > 180.f) df = 360.f - df;
                    key[jj] = ((unsigned long long)__float_as_uint(df) << 32) | (unsigned)p;
                } else {
                    key[jj] = ~0ull;
                }
            }
            float mindiff = 0.f;
            float dmax = 0.f;
            #pragma unroll
            for (int k = 0; k < 4; k++) {
                unsigned long long lk = ~0ull;
                #pragma unroll
                for (int jj = 0; jj < 12; jj++) lk = ullmin2(lk, key[jj]);
                #pragma unroll
                for (int off = 16; off; off >>= 1)
                    lk = ullmin2(lk, __shfl_xor_sync(0xffffffffu, lk, off));
                int widx = (int)(lk & 0xffffffffu);
                if (k == 0) mindiff = __uint_as_float((unsigned)(lk >> 32));
                dmax = fmaxf(dmax, sdist[widx]);
                #pragma unroll
                for (int jj = 0; jj < 12; jj++) if (key[jj] == lk) key[jj] = ~0ull;
            }
            float dm = (mindiff > 3.0f) ? 1e-6f : dmax;
            dm = fmaxf(dm, 1e-6f);
            if (lane == 0) sdm[bin] = dm;
        }
        __syncthreads();

        if (threadIdx.x < NBINS)
            g_dist[(size_t)pairIdx * NBINS + threadIdx.x] = sdm[threadIdx.x];

        // warp 0: iou + centerness + align metric
        if (warp == 0) {
            float smin = 0.f, smax = 0.f, mn = 1e30f, mx = 0.f;
            const float* pb = pd_bboxes + ((size_t)b*NA + a) * NBINS;
            for (int e = lane; e < NBINS; e += 32) {
                float t = sdm[e], p = pb[e];
                smin += fmaxf(fminf(t, p), 1e-6f);
                smax += fmaxf(t, p);
                mn = fminf(mn, t);
                mx = fmaxf(mx, t);
            }
            #pragma unroll
            for (int off = 16; off; off >>= 1) {
                smin += __shfl_xor_sync(0xffffffffu, smin, off);
                smax += __shfl_xor_sync(0xffffffffu, smax, off);
                mn = fminf(mn, __shfl_xor_sync(0xffffffffu, mn, off));
                mx = fmaxf(mx, __shfl_xor_sync(0xffffffffu, mx, off));
            }
            if (lane == 0) {
                float iou = smin / smax;
                float score = pd_scores[((size_t)b*NA + a) * NC + label];
                g_overlaps[pairIdx] = iou;
                g_align[pairIdx]    = score * iou * iou * iou;
                g_cent[pairIdx]     = sqrtf(mn / mx);
            }
        }
        __syncthreads();
    }
}

// ---------------------------------------------------------------------------
// K3: top-13 per GT over its live list (SMEM resident), exact JAX ties
//     (value desc, index asc) via key = align_bits<<32 | (NA - a)
// ---------------------------------------------------------------------------
__global__ __launch_bounds__(256) void k_topk(const float* __restrict__ mask_gt) {
    int bm = blockIdx.x;
    if (mask_gt[bm] == 0.f) return;
    int cnt = g_cnt[bm];
    if (cnt == 0) return;
    if (cnt > MAXL) cnt = MAXL;
    int tid = threadIdx.x;

    __shared__ unsigned long long sk[MAXL];
    __shared__ unsigned long long sred[8];
    __shared__ unsigned long long sbest;

    const int* la = g_liveA + bm*MAXL;
    for (int j = tid; j < cnt; j += 256) {
        int a = la[j];
        float v = g_align[bm*NA + a];
        sk[j] = ((unsigned long long)__float_as_uint(v) << 32) | (unsigned)(NA - a);
    }
    __syncthreads();

    int b = bm / NM, m = bm % NM;
    int kmax = cnt < 13 ? cnt : 13;
    for (int k = 0; k < kmax; k++) {
        unsigned long long best = 0;
        for (int j = tid; j < cnt; j += 256) best = ullmax2(best, sk[j]);
        #pragma unroll
        for (int off = 16; off; off >>= 1)
            best = ullmax2(best, __shfl_xor_sync(0xffffffffu, best, off));
        if ((tid & 31) == 0) sred[tid >> 5] = best;
        __syncthreads();
        if (tid == 0) {
            unsigned long long b2 = 0;
            #pragma unroll
            for (int w = 0; w < 8; w++) b2 = ullmax2(b2, sred[w]);
            sbest = b2;
        }
        __syncthreads();
        unsigned long long B = sbest;
        if (B == 0) break;   // no positive align left; reference padding picks carry mask_pos=0
        for (int j = tid; j < cnt; j += 256) if (sk[j] == B) sk[j] = 0;
        if (tid == 0) {
            int a = NA - (int)(B & 0xffffffffu);
            atomicOr(&g_topkbits[b*NA + a], 1u << m);
        }
        __syncthreads();
    }
}

// ---------------------------------------------------------------------------
// K4: per-anchor resolution + most outputs (+ pos maxima via atomicMax)
// ---------------------------------------------------------------------------
__global__ __launch_bounds__(256) void k_assign(
    const int*   __restrict__ gt_labels,
    const float* __restrict__ gt_bboxes,
    float* __restrict__ out)
{
    int t = blockIdx.x * blockDim.x + threadIdx.x;
    if (t >= BSNA) return;
    int b = t / NA, a = t % NA;

    unsigned tb = g_topkbits[t];
    int fg = __popc(tb);
    unsigned fin = tb;
    if (fg > 1) {
        unsigned inb = g_inbits[t];
        float best = -1.f; int bi = 0;
        #pragma unroll
        for (int m = 0; m < NM; m++) {
            float o = ((inb >> m) & 1u) ? g_overlaps[(b*NM+m)*NA + a] : 0.f;
            if (o > best) { best = o; bi = m; }   // first max kept
        }
        fin = 1u << bi;
    }
    g_finbits[t] = fin;

    int tgt = fin ? (__ffs(fin) - 1) : 0;
    out[FG_OFF + t]  = fin ? 1.f : 0.f;
    out[TGI_OFF + t] = (float)tgt;
    int lbl = gt_labels[b*NM + tgt]; if (lbl < 0) lbl = 0;
    out[TL_OFF + t] = (float)lbl;
    const float4* gb4 = (const float4*)(gt_bboxes);
    ((float4*)(out + TB_OFF))[t] = gb4[b*NM + tgt];

    if (fin) {
        int idx = (b*NM + tgt)*NA + a;
        out[MPB_OFF + idx]  = 1.f;
        out[CENT_OFF + idx] = g_cent[idx];
        float al = g_align[idx];
        float ov = g_overlaps[idx];
        atomicMax(&g_posA[b*NM + tgt], __float_as_uint(al));
        atomicMax(&g_posO[b*NM + tgt], __float_as_uint(ov));
        const float* src = g_dist + (size_t)idx * NBINS;
        float* dst = out + GTDIST_OFF + (size_t)idx * NBINS;
        #pragma unroll
        for (int e = 0; e < NBINS; e++) dst[e] = src[e];
    }
}

// ---------------------------------------------------------------------------
// K5: norm_align + one-hot target_scores (positives only)
// ---------------------------------------------------------------------------
__global__ __launch_bounds__(256) void k_scores(
    const int* __restrict__ gt_labels,
    float* __restrict__ out)
{
    int t = blockIdx.x * blockDim.x + threadIdx.x;
    if (t >= BSNA) return;
    unsigned fin = g_finbits[t];
    if (!fin) return;                 // TS row already zero
    int b = t / NA, a = t % NA;
    int m = __ffs(fin) - 1;
    int bm = b*NM + m;
    int idx = bm*NA + a;
    float am = g_align[idx];
    float norm = am * __uint_as_float(g_posO[bm]) / (__uint_as_float(g_posA[bm]) + 1e-9f);
    int lbl = gt_labels[bm]; if (lbl < 0) lbl = 0;
    out[TS_OFF + (size_t)t * NC + lbl] = norm;
}

// ---------------------------------------------------------------------------
extern "C" void kernel_launch(void* const* d_in, const int* in_sizes, int n_in,
                              void* d_out, int out_size) {
    const float* pd_scores = (const float*)d_in[0];
    const float* pd_bboxes = (const float*)d_in[1];
    const float* anc       = (const float*)d_in[2];
    const int*   gt_labels = (const int*)  d_in[3];
    const float* gt_bboxes = (const float*)d_in[4];
    const float* mask_gt   = (const float*)d_in[5];
    const float* gt_coor   = (const float*)d_in[6];
    float* out = (float*)d_out;

    k_zero<<<(OUT_VEC4 + 255)/256, 256>>>((float4*)out);
    k_compact<<<(BSNA + 255)/256, 256>>>(anc, gt_bboxes, mask_gt);
    dim3 g1(64, NBM);
    k_pairs<<<g1, 128>>>(pd_scores, pd_bboxes, anc, gt_labels, gt_coor);
    k_topk<<<NBM, 256>>>(mask_gt);
    k_assign<<<(BSNA + 255)/256, 256>>>(gt_labels, gt_bboxes, out);
    k_scores<<<(BSNA + 255)/256, 256>>>(gt_labels, out);
}